// round 11
// baseline (speedup 1.0000x reference)
#include <cuda_runtime.h>

typedef unsigned long long u64;

#define NQ     10
#define NGEN   4
#define QDEPTH 6
#define WPB    4   // warps per block

// Parity-of-adjacent-pairs mask for 5-bit k: bit k = popc(k & (k>>1)) & 1.
#define MK_CONST 0x4748B848u
constexpr unsigned mk_check() {
    unsigned m = 0;
    for (int k = 0; k < 32; ++k) {
        int p = 0;
        for (int bb = 0; bb < 4; ++bb) p ^= ((k >> bb) & 1) & ((k >> (bb + 1)) & 1);
        m |= (unsigned)p << k;
    }
    return m;
}
static_assert(mk_check() == MK_CONST, "MK mask mismatch");

// ---- packed f32x2 helpers (SASS FFMA2 — PTX-only on sm_103a) ----
__device__ __forceinline__ u64 fma2(u64 a, u64 b, u64 c) {
    u64 d; asm("fma.rn.f32x2 %0, %1, %2, %3;" : "=l"(d) : "l"(a), "l"(b), "l"(c)); return d;
}
__device__ __forceinline__ u64 mul2(u64 a, u64 b) {
    u64 d; asm("mul.rn.f32x2 %0, %1, %2;" : "=l"(d) : "l"(a), "l"(b)); return d;
}
__device__ __forceinline__ u64 pack2(float lo, float hi) {
    u64 d; asm("mov.b64 %0, {%1, %2};" : "=l"(d) : "f"(lo), "f"(hi)); return d;
}
__device__ __forceinline__ void unpack2(u64 v, float& lo, float& hi) {
    asm("mov.b64 {%0, %1}, %2;" : "=f"(lo), "=f"(hi) : "l"(v));
}
__device__ __forceinline__ u64 swap32(u64 v) {
    return (v << 32) | (v >> 32);
}

// ---- RY via shear/lifting: 3 FMA per pair. Rotation phi: nt=-tan(phi/2), sn=sin(phi).
// x' = x + nt*y ; y' = y + sn*x' ; x'' = x' + nt*y'  ==  [c,-s; s,c]
template<int M>
__device__ __forceinline__ void ry2_shear(u64 (&v)[32], u64 nt, u64 sn) {
    #pragma unroll
    for (int k = 0; k < 32; ++k) if (!(k & M)) {
        const int j = k | M;
        u64 a0 = v[k], a1 = v[j];
        a0 = fma2(nt, a1, a0);
        a1 = fma2(sn, a0, a1);
        a0 = fma2(nt, a1, a0);
        v[k] = a0; v[j] = a1;
    }
}

// ---- RX packed: c=cos(phi), sv=(s,-s) with s=sin(phi).
// new_a0 = (c*a0r + s*a1i, c*a0i - s*a1r) = fma2(sv, swap(a1), mul2(cc, a0))
// new_a1 = (c*a1r + s*a0i, c*a1i - s*a0r) = fma2(sv, swap(a0), mul2(cc, a1))
template<int M>
__device__ __forceinline__ void rx2p(u64 (&v)[32], u64 cc, u64 sv) {
    #pragma unroll
    for (int k = 0; k < 32; ++k) if (!(k & M)) {
        const int j = k | M;
        u64 a0 = v[k], a1 = v[j];
        u64 s0 = swap32(a0), s1 = swap32(a1);
        v[k] = fma2(sv, s1, mul2(cc, a0));
        v[j] = fma2(sv, s0, mul2(cc, a1));
    }
}

template<int M>
__device__ __forceinline__ float exv(const u64 (&v)[32]) {
    u64 acc0 = 0ull, acc1 = 0ull, acc2 = 0ull, acc3 = 0ull;
    #pragma unroll
    for (int k = 0; k < 32; k += 4) {
        acc0 = fma2(v[k + 0], v[(k + 0) ^ M], acc0);
        acc1 = fma2(v[k + 1], v[(k + 1) ^ M], acc1);
        acc2 = fma2(v[k + 2], v[(k + 2) ^ M], acc2);
        acc3 = fma2(v[k + 3], v[(k + 3) ^ M], acc3);
    }
    float l0, h0, l1, h1, l2, h2, l3, h3;
    unpack2(acc0, l0, h0); unpack2(acc1, l1, h1);
    unpack2(acc2, l2, h2); unpack2(acc3, l3, h3);
    return (l0 + h0) + (l1 + h1) + ((l2 + h2) + (l3 + h3));
}

__device__ __forceinline__ void cz_apply(u64 (&v)[32], unsigned sgn) {
    #pragma unroll
    for (int k = 0; k < 32; ++k)
        v[k] ^= (sgn & (1u << k)) ? 0x8000000080000000ull : 0ull;
}

// 32x32 warp transpose through padded smem (stride-34 u64 rows: conflict-free).
__device__ __forceinline__ void transpose(u64 (&v)[32], u64* t, unsigned lane) {
    __syncwarp();
    #pragma unroll
    for (int r = 0; r < 32; r += 2)
        *reinterpret_cast<ulonglong2*>(t + lane * 34u + r) = make_ulonglong2(v[r], v[r + 1]);
    __syncwarp();
    #pragma unroll
    for (int k = 0; k < 32; ++k)
        v[k] = t[k * 34u + lane];
}

// 5 shear-RY gates using precomputed smem consts at indices base..base+4
// (wire order maps to M = 16,8,4,2,1 in both layouts)
__device__ __forceinline__ void half5(u64 (&v)[32],
                                      const float* __restrict__ snt,
                                      const float* __restrict__ ssn,
                                      int base) {
    float x;
    u64 nt, sn;
    x = snt[base + 0]; nt = pack2(x, x); x = ssn[base + 0]; sn = pack2(x, x);
    ry2_shear<16>(v, nt, sn);
    x = snt[base + 1]; nt = pack2(x, x); x = ssn[base + 1]; sn = pack2(x, x);
    ry2_shear<8>(v, nt, sn);
    x = snt[base + 2]; nt = pack2(x, x); x = ssn[base + 2]; sn = pack2(x, x);
    ry2_shear<4>(v, nt, sn);
    x = snt[base + 3]; nt = pack2(x, x); x = ssn[base + 3]; sn = pack2(x, x);
    ry2_shear<2>(v, nt, sn);
    x = snt[base + 4]; nt = pack2(x, x); x = ssn[base + 4]; sn = pack2(x, x);
    ry2_shear<1>(v, nt, sn);
}

// one init wire: shear-RY then packed RX, consts from smem index idx
template<int M>
__device__ __forceinline__ void init_wire(u64 (&v)[32],
                                          const float* __restrict__ int_,
                                          const float* __restrict__ is_,
                                          const float* __restrict__ ic_,
                                          int idx) {
    float tn = int_[idx], s = is_[idx], c = ic_[idx];
    u64 nt = pack2(tn, tn), sn = pack2(s, s);
    ry2_shear<M>(v, nt, sn);
    u64 cc = pack2(c, c), sv = pack2(s, -s);
    rx2p<M>(v, cc, sv);
}

// ===== Fused kernel: one warp per (b, g) =====
// Layout A: i = lane*32 + k (register wires 5..9)
// Layout B: i = k*32 + lane (register wires 0..4)
__global__ void __launch_bounds__(32 * WPB, 4)
qgen_fused(const float* __restrict__ noise,
           const float* __restrict__ qp,
           float* __restrict__ out, int batch)
{
    __shared__ u64   tile[WPB][32 * 34];
    __shared__ float tnt[WPB][64], tsn[WPB][64];   // tail shear consts
    __shared__ float int_[WPB][16], is_[WPB][16], ic_[WPB][16]; // init consts

    const unsigned lane = threadIdx.x & 31u;
    const unsigned w    = threadIdx.x >> 5;
    const unsigned wid  = blockIdx.x * WPB + w;
    const unsigned b    = wid >> 2;          // 4 gens of one sample share a block
    const unsigned g    = wid & 3u;
    if ((int)b >= batch) return;
    u64* t = tile[w];

    // ---- lane-parallel const precompute ----
    // RY(theta) rotates by phi = theta/2. One sincosf(theta/4) gives:
    //   nt = -tan(theta/4), s = sin(theta/2) = 2 s4 c4, c = cos(theta/2) = 1 - 2 s4^2
    const float* wg = qp + g * (QDEPTH * NQ);
    {
        float a0 = wg[lane];                       // tail idx 0..31
        float s4, c4;
        __sincosf(0.25f * a0, &s4, &c4);
        tnt[w][lane] = -__fdividef(s4, c4);
        tsn[w][lane] = 2.0f * s4 * c4;
        const int i1 = 32 + (int)lane;             // tail idx 32..59
        if (i1 < QDEPTH * NQ) {
            float a1 = wg[i1];
            __sincosf(0.25f * a1, &s4, &c4);
            tnt[w][i1] = -__fdividef(s4, c4);
            tsn[w][i1] = 2.0f * s4 * c4;
        }
        if (lane < NQ) {                           // init angles
            float an = noise[(size_t)b * NQ + lane];
            __sincosf(0.25f * an, &s4, &c4);
            int_[w][lane] = -__fdividef(s4, c4);
            is_[w][lane]  = 2.0f * s4 * c4;
            ic_[w][lane]  = fmaf(-2.0f * s4, s4, 1.0f);
        }
    }
    __syncwarp();
    const float* NT = tnt[w];
    const float* SN = tsn[w];
    const float* IT = int_[w];
    const float* IS = is_[w];
    const float* IC = ic_[w];

    const unsigned pL   = (__popc(lane & (lane >> 1)) & 1) ? 0xFFFFFFFFu : 0u;
    const unsigned sgnA = MK_CONST ^ pL ^ ((lane & 1u)        ? 0xFFFF0000u : 0u);
    const unsigned sgnB = MK_CONST ^ pL ^ (((lane >> 4) & 1u) ? 0xAAAAAAAAu : 0u);

    // ---- state |0...0>, layout A ----
    u64 v[32];
    #pragma unroll
    for (int k = 0; k < 32; ++k) v[k] = 0ull;
    if (lane == 0) v[0] = pack2(1.0f, 0.0f);

    // ---- init: RY(n_q)+RX(n_q) on all wires ----
    init_wire<16>(v, IT, IS, IC, 5);   // layout A: wires 5..9
    init_wire<8>(v,  IT, IS, IC, 6);
    init_wire<4>(v,  IT, IS, IC, 7);
    init_wire<2>(v,  IT, IS, IC, 8);
    init_wire<1>(v,  IT, IS, IC, 9);
    transpose(v, t, lane);             // -> layout B
    init_wire<16>(v, IT, IS, IC, 0);   // wires 0..4
    init_wire<8>(v,  IT, IS, IC, 1);
    init_wire<4>(v,  IT, IS, IC, 2);
    init_wire<2>(v,  IT, IS, IC, 3);
    init_wire<1>(v,  IT, IS, IC, 4);

    // ---- layers (start in layout B) ----
    #pragma unroll
    for (int l = 0; l < QDEPTH; l += 2) {
        const int w0 = l * NQ;
        half5(v, NT, SN, w0 + 0);      // layout B: wires 0..4
        transpose(v, t, lane);         // -> A
        half5(v, NT, SN, w0 + 5);      // wires 5..9
        cz_apply(v, sgnA);
        const int w1 = w0 + NQ;
        half5(v, NT, SN, w1 + 5);      // layout A: wires 5..9
        transpose(v, t, lane);         // -> B
        half5(v, NT, SN, w1 + 0);      // wires 0..4
        cz_apply(v, sgnB);
    }

    // ---- expectations ----
    float e[10];
    e[0] = exv<16>(v); e[1] = exv<8>(v); e[2] = exv<4>(v);   // layout B: wires 0..4
    e[3] = exv<2>(v);  e[4] = exv<1>(v);
    transpose(v, t, lane);                                    // -> A
    e[5] = exv<16>(v); e[6] = exv<8>(v); e[7] = exv<4>(v);   // wires 5..9
    e[8] = exv<2>(v);  e[9] = exv<1>(v);

    #pragma unroll
    for (int q = 0; q < 10; ++q) {
        float a = e[q];
        #pragma unroll
        for (int o = 16; o; o >>= 1) a += __shfl_xor_sync(0xffffffffu, a, o);
        e[q] = a;
    }
    if (lane == 0) {
        float* ob = out + (size_t)b * (NGEN * NQ) + (size_t)g * NQ;
        #pragma unroll
        for (int q = 0; q < 10; ++q) ob[q] = e[q];
    }
}

extern "C" void kernel_launch(void* const* d_in, const int* in_sizes, int n_in,
                              void* d_out, int out_size) {
    const float* noise = (const float*)d_in[0];   // (BATCH, NQ) fp32
    const float* qp    = (const float*)d_in[1];   // (NGEN, QDEPTH, NQ) fp32
    float* out = (float*)d_out;                   // (BATCH, NGEN*NQ) fp32

    int batch  = in_sizes[0] / NQ;
    int warps  = batch * NGEN;
    int blocks = (warps + WPB - 1) / WPB;
    qgen_fused<<<blocks, 32 * WPB>>>(noise, qp, out, batch);
}